// round 5
// baseline (speedup 1.0000x reference)
#include <cuda_runtime.h>

// Problem geometry
#define IMG_H 512
#define IMG_W 512
#define NBATCH 32
#define CH_STRIDE (NBATCH * IMG_H * IMG_W)   // per-channel stride (elements)
#define B_STRIDE  (IMG_H * IMG_W)            // per-batch stride

// Tile geometry: 64 wide x 32 high output tile, +1 halo each side.
#define TW 64
#define TH 32
#define TROWS (TH + 2)      // 34
#define TCOLS (TW + 2)      // 66 valid columns
#define PITCH 68            // padded to multiple of 4 floats for float4 LDS alignment
#define FELEMS (TROWS * PITCH)  // 2312 floats per field
#define NF 10               // s0..s3, f0..f5
#define W_OFF (NF * FELEMS)
#define SMEM_FLOATS (W_OFF + 112)   // + 108 kernel weights, padded

// cbrt via MUFU lg2/ex2: x >= 0 always here (uniform [0,1) inputs).
// x==0: lg2 -> -inf, ex2(-inf) -> 0. Rel err ~1e-6, fine for 1e-3 gate.
__device__ __forceinline__ float cbrt_fast(float x) {
    float lg;
    asm("lg2.approx.f32 %0, %1;" : "=f"(lg) : "f"(x));
    float e = lg * 0.33333333333333f;
    float r;
    asm("ex2.approx.f32 %0, %1;" : "=f"(r) : "f"(e));
    return r;
}

// Accumulate one 3x3 conv over a 4-wide x 2-high output block.
// R,C: smem coords of the top-left of the 4x6 input window (conv window of
// output rows R..R+1, cols C..C+3, where output (oy,ox) maps to smem (oy+1,ox+1)).
__device__ __forceinline__ void conv_acc(const float* __restrict__ t, int R, int C,
                                         const float* __restrict__ w, float acc[2][4]) {
    float wr[9];
    #pragma unroll
    for (int k = 0; k < 9; k++) wr[k] = w[k];
    #pragma unroll
    for (int r = 0; r < 4; r++) {
        const float* row = t + (R + r) * PITCH + C;
        float4 a  = *reinterpret_cast<const float4*>(row);      // cols C..C+3 (16B aligned)
        float2 bb = *reinterpret_cast<const float2*>(row + 4);  // cols C+4,C+5 (8B aligned)
        const float v[6] = {a.x, a.y, a.z, a.w, bb.x, bb.y};
        #pragma unroll
        for (int oy = 0; oy < 2; oy++) {
            const int dy = r - oy;           // input row r feeds output row oy with tap dy
            if (dy >= 0 && dy < 3) {
                #pragma unroll
                for (int ox = 0; ox < 4; ox++) {
                    acc[oy][ox] = fmaf(wr[dy * 3 + 0], v[ox + 0], acc[oy][ox]);
                    acc[oy][ox] = fmaf(wr[dy * 3 + 1], v[ox + 1], acc[oy][ox]);
                    acc[oy][ox] = fmaf(wr[dy * 3 + 2], v[ox + 2], acc[oy][ox]);
                }
            }
        }
    }
}

__global__ __launch_bounds__(256, 2)
void fused_bleed(const float* __restrict__ src, const float* __restrict__ ker,
                 float* __restrict__ out) {
    extern __shared__ float sm[];
    float* w = sm + W_OFF;

    const int tid = threadIdx.x;
    const int x0 = blockIdx.x * TW;
    const int y0 = blockIdx.y * TH;
    const int b  = blockIdx.z;

    if (tid < 108) w[tid] = ker[tid];

    const float* base = src + b * B_STRIDE;

    // ---- Load halo tiles for all 4 channels; compute the 6 inter fields inline.
    // inter(i,j) = (s_j^0.5 * s_i)^(2/3) = cbrt(s_j) * cbrt(s_i)^2
    for (int idx = tid; idx < TROWS * TCOLS; idx += 256) {
        const int ly = idx / TCOLS;
        const int lx = idx - ly * TCOLS;
        const int gy = y0 - 1 + ly;
        const int gx = x0 - 1 + lx;
        float s0 = 0.f, s1 = 0.f, s2 = 0.f, s3 = 0.f;
        if ((unsigned)gy < (unsigned)IMG_H && (unsigned)gx < (unsigned)IMG_W) {
            const int g = gy * IMG_W + gx;
            s0 = base[g];
            s1 = base[g + CH_STRIDE];
            s2 = base[g + 2 * CH_STRIDE];
            s3 = base[g + 3 * CH_STRIDE];
        }
        const int o = ly * PITCH + lx;
        sm[o]              = s0;
        sm[o + FELEMS]     = s1;
        sm[o + 2 * FELEMS] = s2;
        sm[o + 3 * FELEMS] = s3;
        const float c0 = cbrt_fast(s0), c1 = cbrt_fast(s1);
        const float c2 = cbrt_fast(s2), c3 = cbrt_fast(s3);
        const float q0 = c0 * c0, q1 = c1 * c1, q2 = c2 * c2, q3 = c3 * c3;
        sm[o + 4 * FELEMS] = c1 * q0;   // f0: pair (i=0, j=1) -> K1
        sm[o + 5 * FELEMS] = c0 * q1;   // f1: pair (1,0) -> K3
        sm[o + 6 * FELEMS] = c2 * q1;   // f2: pair (1,2) -> K5
        sm[o + 7 * FELEMS] = c1 * q2;   // f3: pair (2,1) -> K7
        sm[o + 8 * FELEMS] = c3 * q2;   // f4: pair (2,3) -> K9
        sm[o + 9 * FELEMS] = c2 * q3;   // f5: pair (3,2) -> K11
    }
    __syncthreads();

    // ---- Compute phase: each thread owns a 4-wide x 2-high block for all 4 channels.
    const int tx = tid & 15;
    const int ty = tid >> 4;
    const int R = ty * 2;   // tile-relative output row base
    const int C = tx * 4;   // tile-relative output col base (multiple of 4)
    float* outb = out + b * B_STRIDE + (y0 + R) * IMG_W + (x0 + C);

    // out0 = s0 - conv(s1,K0) - conv(f0,K1)
    {
        float acc[2][4] = {};
        conv_acc(sm + 1 * FELEMS, R, C, w + 0, acc);
        conv_acc(sm + 4 * FELEMS, R, C, w + 9, acc);
        #pragma unroll
        for (int oy = 0; oy < 2; oy++) {
            const float* s = sm + 0 * FELEMS + (R + 1 + oy) * PITCH + (C + 1);
            float4 v = { s[0] - acc[oy][0], s[1] - acc[oy][1],
                         s[2] - acc[oy][2], s[3] - acc[oy][3] };
            *reinterpret_cast<float4*>(outb + 0 * CH_STRIDE + oy * IMG_W) = v;
        }
    }
    // out1 = s1 - conv(s0,K2) - conv(f1,K3) - conv(s2,K4) - conv(f2,K5)
    {
        float acc[2][4] = {};
        conv_acc(sm + 0 * FELEMS, R, C, w + 18, acc);
        conv_acc(sm + 5 * FELEMS, R, C, w + 27, acc);
        conv_acc(sm + 2 * FELEMS, R, C, w + 36, acc);
        conv_acc(sm + 6 * FELEMS, R, C, w + 45, acc);
        #pragma unroll
        for (int oy = 0; oy < 2; oy++) {
            const float* s = sm + 1 * FELEMS + (R + 1 + oy) * PITCH + (C + 1);
            float4 v = { s[0] - acc[oy][0], s[1] - acc[oy][1],
                         s[2] - acc[oy][2], s[3] - acc[oy][3] };
            *reinterpret_cast<float4*>(outb + 1 * CH_STRIDE + oy * IMG_W) = v;
        }
    }
    // out2 = s2 - conv(s1,K6) - conv(f3,K7) - conv(s3,K8) - conv(f4,K9)
    {
        float acc[2][4] = {};
        conv_acc(sm + 1 * FELEMS, R, C, w + 54, acc);
        conv_acc(sm + 7 * FELEMS, R, C, w + 63, acc);
        conv_acc(sm + 3 * FELEMS, R, C, w + 72, acc);
        conv_acc(sm + 8 * FELEMS, R, C, w + 81, acc);
        #pragma unroll
        for (int oy = 0; oy < 2; oy++) {
            const float* s = sm + 2 * FELEMS + (R + 1 + oy) * PITCH + (C + 1);
            float4 v = { s[0] - acc[oy][0], s[1] - acc[oy][1],
                         s[2] - acc[oy][2], s[3] - acc[oy][3] };
            *reinterpret_cast<float4*>(outb + 2 * CH_STRIDE + oy * IMG_W) = v;
        }
    }
    // out3 = s3 - conv(s2,K10) - conv(f5,K11)
    {
        float acc[2][4] = {};
        conv_acc(sm + 2 * FELEMS, R, C, w + 90, acc);
        conv_acc(sm + 9 * FELEMS, R, C, w + 99, acc);
        #pragma unroll
        for (int oy = 0; oy < 2; oy++) {
            const float* s = sm + 3 * FELEMS + (R + 1 + oy) * PITCH + (C + 1);
            float4 v = { s[0] - acc[oy][0], s[1] - acc[oy][1],
                         s[2] - acc[oy][2], s[3] - acc[oy][3] };
            *reinterpret_cast<float4*>(outb + 3 * CH_STRIDE + oy * IMG_W) = v;
        }
    }
}

extern "C" void kernel_launch(void* const* d_in, const int* in_sizes, int n_in,
                              void* d_out, int out_size) {
    const float* src = (const float*)d_in[0];   // sources (4,32,512,512,1) fp32
    const float* ker = (const float*)d_in[1];   // kernels (12,3,3) fp32
    float* out = (float*)d_out;

    const size_t smem = SMEM_FLOATS * sizeof(float);  // ~92.9 KB
    cudaFuncSetAttribute((const void*)fused_bleed,
                         cudaFuncAttributeMaxDynamicSharedMemorySize, (int)smem);

    dim3 grid(IMG_W / TW, IMG_H / TH, NBATCH);  // (8, 16, 32)
    fused_bleed<<<grid, 256, smem>>>(src, ker, out);
}

// round 6
// speedup vs baseline: 1.3251x; 1.3251x over previous
#include <cuda_runtime.h>

// Problem geometry
#define IMG_H 512
#define IMG_W 512
#define NBATCH 32
#define CH_STRIDE (NBATCH * IMG_H * IMG_W)   // per-channel stride (elements)
#define B_STRIDE  (IMG_H * IMG_W)            // per-batch stride

// Tile geometry: 64 wide x 16 high output tile, +1 halo each side.
#define TW 64
#define TH 16
#define TROWS (TH + 2)      // 18
#define TCOLS (TW + 2)      // 66 valid columns
#define PITCH 68            // padded so row starts are 16B-aligned for float4 LDS
#define FELEMS (TROWS * PITCH)  // 1224 floats per field
#define NF 10               // s0..s3, f0..f5
#define SMEM_FLOATS (NF * FELEMS)   // 12240 floats = 47.8 KB (static, <48KB)

__constant__ float cw[108];   // 12 3x3 kernels

// cbrt via MUFU lg2/ex2: x >= 0 always here (uniform [0,1) inputs).
// x==0: lg2 -> -inf, ex2(-inf) -> 0. Rel err ~1e-6, fine for 1e-3 gate.
__device__ __forceinline__ float cbrt_fast(float x) {
    float lg;
    asm("lg2.approx.f32 %0, %1;" : "=f"(lg) : "f"(x));
    float e = lg * 0.33333333333333f;
    float r;
    asm("ex2.approx.f32 %0, %1;" : "=f"(r) : "f"(e));
    return r;
}

__device__ __forceinline__ void ldrow(const float* __restrict__ row, float v[6]) {
    float4 a  = *reinterpret_cast<const float4*>(row);      // 16B aligned
    float2 bb = *reinterpret_cast<const float2*>(row + 4);  // 8B aligned
    v[0] = a.x; v[1] = a.y; v[2] = a.z; v[3] = a.w; v[4] = bb.x; v[5] = bb.y;
}

// 3x3 conv over a 4-wide x 1-high output block, one accumulator.
// t+off points at the window top-left (3 rows x 6 cols). Optionally captures
// the center row (the field's own pixel values) into cen[4].
__device__ __forceinline__ void conv1(const float* __restrict__ t, int off, int wb,
                                      float acc[4], float* cen) {
    #pragma unroll
    for (int r = 0; r < 3; r++) {
        float v[6];
        ldrow(t + off + r * PITCH, v);
        if (cen && r == 1) { cen[0] = v[1]; cen[1] = v[2]; cen[2] = v[3]; cen[3] = v[4]; }
        #pragma unroll
        for (int ox = 0; ox < 4; ox++) {
            acc[ox] = fmaf(cw[wb + r * 3 + 0], v[ox + 0], acc[ox]);
            acc[ox] = fmaf(cw[wb + r * 3 + 1], v[ox + 1], acc[ox]);
            acc[ox] = fmaf(cw[wb + r * 3 + 2], v[ox + 2], acc[ox]);
        }
    }
}

// Same window, two (weight, accumulator) pairs — shares the row loads.
__device__ __forceinline__ void conv2(const float* __restrict__ t, int off,
                                      int wbA, float accA[4],
                                      int wbB, float accB[4], float* cen) {
    #pragma unroll
    for (int r = 0; r < 3; r++) {
        float v[6];
        ldrow(t + off + r * PITCH, v);
        if (cen && r == 1) { cen[0] = v[1]; cen[1] = v[2]; cen[2] = v[3]; cen[3] = v[4]; }
        #pragma unroll
        for (int ox = 0; ox < 4; ox++) {
            accA[ox] = fmaf(cw[wbA + r * 3 + 0], v[ox + 0], accA[ox]);
            accA[ox] = fmaf(cw[wbA + r * 3 + 1], v[ox + 1], accA[ox]);
            accA[ox] = fmaf(cw[wbA + r * 3 + 2], v[ox + 2], accA[ox]);
            accB[ox] = fmaf(cw[wbB + r * 3 + 0], v[ox + 0], accB[ox]);
            accB[ox] = fmaf(cw[wbB + r * 3 + 1], v[ox + 1], accB[ox]);
            accB[ox] = fmaf(cw[wbB + r * 3 + 2], v[ox + 2], accB[ox]);
        }
    }
}

__device__ __forceinline__ void store4(float* p, const float cen[4], const float acc[4]) {
    float4 v = { cen[0] - acc[0], cen[1] - acc[1], cen[2] - acc[2], cen[3] - acc[3] };
    *reinterpret_cast<float4*>(p) = v;
}

__global__ __launch_bounds__(256, 4)
void fused_bleed(const float* __restrict__ src, float* __restrict__ out) {
    __shared__ float sm[SMEM_FLOATS];

    const int tid = threadIdx.x;
    const int x0 = blockIdx.x * TW;
    const int y0 = blockIdx.y * TH;
    const int b  = blockIdx.z;

    const float* base = src + b * B_STRIDE;

    // ---- Load halo tiles for all 4 channels; compute the 6 inter fields inline.
    // inter(i,j) = (s_j^0.5 * s_i)^(2/3) = cbrt(s_j) * cbrt(s_i)^2
    for (int idx = tid; idx < TROWS * TCOLS; idx += 256) {
        const int ly = idx / TCOLS;
        const int lx = idx - ly * TCOLS;
        const int gy = y0 - 1 + ly;
        const int gx = x0 - 1 + lx;
        float s0 = 0.f, s1 = 0.f, s2 = 0.f, s3 = 0.f;
        if ((unsigned)gy < (unsigned)IMG_H && (unsigned)gx < (unsigned)IMG_W) {
            const int g = gy * IMG_W + gx;
            s0 = base[g];
            s1 = base[g + CH_STRIDE];
            s2 = base[g + 2 * CH_STRIDE];
            s3 = base[g + 3 * CH_STRIDE];
        }
        const int o = ly * PITCH + lx;
        sm[o]              = s0;
        sm[o + FELEMS]     = s1;
        sm[o + 2 * FELEMS] = s2;
        sm[o + 3 * FELEMS] = s3;
        const float c0 = cbrt_fast(s0), c1 = cbrt_fast(s1);
        const float c2 = cbrt_fast(s2), c3 = cbrt_fast(s3);
        const float q0 = c0 * c0, q1 = c1 * c1, q2 = c2 * c2, q3 = c3 * c3;
        sm[o + 4 * FELEMS] = c1 * q0;   // f0: (i=0,j=1) -> K1
        sm[o + 5 * FELEMS] = c0 * q1;   // f1: (1,0) -> K3
        sm[o + 6 * FELEMS] = c2 * q1;   // f2: (1,2) -> K5
        sm[o + 7 * FELEMS] = c1 * q2;   // f3: (2,1) -> K7
        sm[o + 8 * FELEMS] = c3 * q2;   // f4: (2,3) -> K9
        sm[o + 9 * FELEMS] = c2 * q3;   // f5: (3,2) -> K11
    }
    __syncthreads();

    // ---- Compute phase: each thread owns a 4-wide x 1-high block, all 4 channels.
    const int tx = tid & 15;
    const int ty = tid >> 4;
    const int off = ty * PITCH + tx * 4;   // window top-left in smem (output row ty)
    float* outp = out + b * B_STRIDE + (y0 + ty) * IMG_W + (x0 + tx * 4);

    float acc0[4] = {}, acc1[4] = {}, acc2[4] = {}, acc3[4] = {};
    float cen0[4], cen1[4], cen2[4], cen3[4];

    // s0: feeds out1 (K2); center = s0 pixels for out0.
    conv1(sm + 0 * FELEMS, off, 18, acc1, cen0);
    // s1: feeds out0 (K0) and out2 (K6); center for out1.
    conv2(sm + 1 * FELEMS, off, 0, acc0, 54, acc2, cen1);
    // f0 -> out0 (K1); retire out0.
    conv1(sm + 4 * FELEMS, off, 9, acc0, nullptr);
    store4(outp + 0 * CH_STRIDE, cen0, acc0);
    // f1 -> out1 (K3)
    conv1(sm + 5 * FELEMS, off, 27, acc1, nullptr);
    // s2: feeds out1 (K4) and out3 (K10); center for out2.
    conv2(sm + 2 * FELEMS, off, 36, acc1, 90, acc3, cen2);
    // f2 -> out1 (K5); retire out1.
    conv1(sm + 6 * FELEMS, off, 45, acc1, nullptr);
    store4(outp + 1 * CH_STRIDE, cen1, acc1);
    // f3 -> out2 (K7)
    conv1(sm + 7 * FELEMS, off, 63, acc2, nullptr);
    // s3: feeds out2 (K8); center for out3.
    conv1(sm + 3 * FELEMS, off, 72, acc2, cen3);
    // f4 -> out2 (K9); retire out2.
    conv1(sm + 8 * FELEMS, off, 81, acc2, nullptr);
    store4(outp + 2 * CH_STRIDE, cen2, acc2);
    // f5 -> out3 (K11); retire out3.
    conv1(sm + 9 * FELEMS, off, 99, acc3, nullptr);
    store4(outp + 3 * CH_STRIDE, cen3, acc3);
}

extern "C" void kernel_launch(void* const* d_in, const int* in_sizes, int n_in,
                              void* d_out, int out_size) {
    const float* src = (const float*)d_in[0];   // sources (4,32,512,512,1) fp32
    const float* ker = (const float*)d_in[1];   // kernels (12,3,3) fp32
    float* out = (float*)d_out;

    // Weights into constant memory (D2D async copy — graph-capturable memcpy node).
    cudaMemcpyToSymbolAsync(cw, ker, 108 * sizeof(float), 0,
                            cudaMemcpyDeviceToDevice, 0);

    dim3 grid(IMG_W / TW, IMG_H / TH, NBATCH);  // (8, 32, 32)
    fused_bleed<<<grid, 256>>>(src, out);
}